// round 3
// baseline (speedup 1.0000x reference)
#include <cuda_runtime.h>
#include <cuda_bf16.h>

// Problem constants (DenseKVMemory: B=1, M=32768, S=512, H=8, D=64)
#define M_   32768
#define S_   512
#define H_   8
#define D_   64
#define HD_  (H_ * D_)          // 512
#define CTX_ (M_ + S_)          // 33280

#define TK        32            // keys per tile
#define QW        8             // queries per warp
#define NW        2             // warps per block
#define BQ        (QW * NW)     // 16 queries per block
#define NTHREADS  64
#define NSPLIT    4
#define NTILES    (CTX_ / TK)            // 1040
#define TPS       (NTILES / NSPLIT)      // 260 tiles per split
#define KST       68            // smem row stride (floats), conflict-free padding

// Output layout: y | new_mem_keys | new_mem_vals | new_write_index
#define OFF_Y   0
#define OFF_MK  (S_ * HD_)                 // 262144
#define OFF_MV  (OFF_MK + M_ * HD_)        // 17039360
#define OFF_WI  (OFF_MV + M_ * HD_)        // 33816576

// Split-K partial scratch (device globals: no allocation allowed)
__device__ float g_pacc[NSPLIT][S_][H_][D_];   // 4 MB
__device__ float g_pm[NSPLIT][S_][H_];
__device__ float g_pl[NSPLIT][S_][H_];

// ---------------- f32x2 packed helpers (Blackwell FFMA2) ----------------
__device__ __forceinline__ void ffma2(unsigned long long& d, unsigned long long a,
                                      unsigned long long b) {
    asm volatile("fma.rn.f32x2 %0, %1, %2, %0;" : "+l"(d) : "l"(a), "l"(b));
}
__device__ __forceinline__ void mul2(unsigned long long& d, unsigned long long a) {
    asm volatile("mul.rn.f32x2 %0, %0, %1;" : "+l"(d) : "l"(a));
}
__device__ __forceinline__ unsigned long long pack2(float x, float y) {
    unsigned long long r;
    asm("mov.b64 %0, {%1, %2};" : "=l"(r) : "f"(x), "f"(y));
    return r;
}
__device__ __forceinline__ float2 unpack2(unsigned long long v) {
    float2 r;
    asm("mov.b64 {%0, %1}, %2;" : "=f"(r.x), "=f"(r.y) : "l"(v));
    return r;
}
__device__ __forceinline__ void cp_async16(void* sdst, const void* gsrc) {
    unsigned sa = (unsigned)__cvta_generic_to_shared(sdst);
    asm volatile("cp.async.cg.shared.global [%0], [%1], 16;" :: "r"(sa), "l"(gsrc));
}

// ---------------- clear-copy: new_mem = mem * keep ----------------
__global__ void copy_clear_kernel(const float4* __restrict__ mk,
                                  const float4* __restrict__ mv,
                                  float4* __restrict__ ok, float4* __restrict__ ov,
                                  const unsigned char* __restrict__ sos) {
    const int i = blockIdx.x * blockDim.x + threadIdx.x;
    const float keep = (sos != nullptr && sos[0]) ? 0.0f : 1.0f;
    if (i < (M_ * HD_) / 4) {
        float4 a = mk[i];
        a.x *= keep; a.y *= keep; a.z *= keep; a.w *= keep;
        ok[i] = a;
        float4 b = mv[i];
        b.x *= keep; b.y *= keep; b.z *= keep; b.w *= keep;
        ov[i] = b;
    }
}

// ---------------- scatter: contiguous slice write at clamped write_index ----------------
__global__ void scatter_kernel(const float4* __restrict__ k4, const float4* __restrict__ v4,
                               float4* __restrict__ ok, float4* __restrict__ ov,
                               const int* __restrict__ wip) {
    const int i = blockIdx.x * blockDim.x + threadIdx.x;
    if (i < (S_ * HD_) / 4) {
        int wi = wip ? *wip : 0;
        int wic = wi < 0 ? 0 : (wi > (M_ - S_) ? (M_ - S_) : wi);  // dynamic_update_slice clamp
        const int base = wic * (HD_ / 4);
        ok[base + i] = k4[i];
        ov[base + i] = v4[i];
    }
}

__global__ void widx_kernel(float* __restrict__ out_wi, const int* __restrict__ wip) {
    int wi = wip ? *wip : 0;
    out_wi[0] = (float)((wi + S_) % M_);
}

// ---------------- flash attention (split-K partials) ----------------
__global__ void __launch_bounds__(NTHREADS)
attn_kernel(const float* __restrict__ memK, const float* __restrict__ memV,
            const float* __restrict__ segK, const float* __restrict__ segV,
            const float* __restrict__ Qg) {
    __shared__ __align__(16) float K_s[2][TK][KST];
    __shared__ __align__(16) float V_s[2][TK][KST];
    __shared__ __align__(16) float Q_s[BQ][D_];
    __shared__ __align__(16) float P_s[NW][QW][TK];

    const int tid  = threadIdx.x;
    const int w    = tid >> 5;
    const int lane = tid & 31;
    const int h    = blockIdx.y;
    const int q0   = blockIdx.x * BQ;
    const int split = blockIdx.z;
    const int t0   = split * TPS;

    // Load + pre-scale Q tile (16 queries x 64)
    #pragma unroll
    for (int r = 0; r < (BQ * D_) / NTHREADS; r++) {
        int i = tid + r * NTHREADS;
        int qi = i >> 6, d = i & 63;
        Q_s[qi][d] = Qg[((q0 + qi) * H_ + h) * D_ + d] * 0.125f;
    }

    const int ch4   = (tid & 15) * 4;     // 16B chunk within a 64-float row
    const int rbase = tid >> 4;           // base row, step 4 per rep

    auto issue_tile = [&](int t, int buf) {
        const int c0 = t * TK;
        const bool mem = (c0 < M_);
        const float* Ksrc = mem ? memK : segK;
        const float* Vsrc = mem ? memV : segV;
        const int row0 = mem ? c0 : (c0 - M_);
        const int gbase = (row0 + rbase) * HD_ + h * D_ + ch4;
        #pragma unroll
        for (int rep = 0; rep < 8; rep++) {
            const int goff = gbase + rep * 4 * HD_;
            cp_async16(&K_s[buf][rbase + 4 * rep][ch4], Ksrc + goff);
            cp_async16(&V_s[buf][rbase + 4 * rep][ch4], Vsrc + goff);
        }
    };

    float m_run[QW], l_run[QW];
    unsigned long long acc2[QW];
    #pragma unroll
    for (int qi = 0; qi < QW; qi++) { m_run[qi] = -1e30f; l_run[qi] = 0.0f; acc2[qi] = 0ull; }

    issue_tile(t0, 0);
    asm volatile("cp.async.commit_group;" ::: "memory");
    __syncthreads();  // Q_s visible to all warps

    for (int tt = 0; tt < TPS; tt++) {
        const int t = t0 + tt;
        const int buf = tt & 1;
        if (tt + 1 < TPS) issue_tile(t + 1, (tt + 1) & 1);
        asm volatile("cp.async.commit_group;" ::: "memory");
        asm volatile("cp.async.wait_group 1;" ::: "memory");
        __syncthreads();

        // ---- S = Q K^T for this lane's key (lane = key row in tile) ----
        const ulonglong2* Kl = (const ulonglong2*)(&K_s[buf][lane][0]);
        unsigned long long sacc[QW];
        #pragma unroll
        for (int qi = 0; qi < QW; qi++) sacc[qi] = 0ull;

        #pragma unroll 4
        for (int i = 0; i < 16; i++) {
            const ulonglong2 kv = Kl[i];
            #pragma unroll
            for (int qi = 0; qi < QW; qi++) {
                const ulonglong2 qv = *((const ulonglong2*)(&Q_s[w * QW + qi][i * 4]));
                ffma2(sacc[qi], kv.x, qv.x);
                ffma2(sacc[qi], kv.y, qv.y);
            }
        }

        const int c = t * TK + lane;
        const bool is_seg = (c >= M_);
        const int skey = c - M_;

        // ---- online softmax ----
        #pragma unroll
        for (int qi = 0; qi < QW; qi++) {
            float2 sp = unpack2(sacc[qi]);
            float s = sp.x + sp.y;
            const int qg = q0 + w * QW + qi;
            if (is_seg && skey >= qg) s = -1e30f;   // causal: key strictly before query
            float tmax = s;
            #pragma unroll
            for (int o = 16; o > 0; o >>= 1)
                tmax = fmaxf(tmax, __shfl_xor_sync(0xffffffffu, tmax, o));
            if (tmax > m_run[qi]) {
                float rs = __expf(m_run[qi] - tmax);
                m_run[qi] = tmax;
                l_run[qi] *= rs;
                mul2(acc2[qi], pack2(rs, rs));
            }
            float p = __expf(s - m_run[qi]);
            float ps = p;
            #pragma unroll
            for (int o = 16; o > 0; o >>= 1)
                ps += __shfl_xor_sync(0xffffffffu, ps, o);
            l_run[qi] += ps;
            P_s[w][qi][lane] = p;
        }
        __syncwarp();

        // ---- PV: lane owns d-pair (2*lane, 2*lane+1) ----
        const int dl = 2 * lane;
        #pragma unroll 2
        for (int jc = 0; jc < 8; jc++) {
            const unsigned long long v0 = *(const unsigned long long*)&V_s[buf][jc * 4 + 0][dl];
            const unsigned long long v1 = *(const unsigned long long*)&V_s[buf][jc * 4 + 1][dl];
            const unsigned long long v2 = *(const unsigned long long*)&V_s[buf][jc * 4 + 2][dl];
            const unsigned long long v3 = *(const unsigned long long*)&V_s[buf][jc * 4 + 3][dl];
            #pragma unroll
            for (int qi = 0; qi < QW; qi++) {
                const float4 p4 = *((const float4*)&P_s[w][qi][jc * 4]);
                ffma2(acc2[qi], pack2(p4.x, p4.x), v0);
                ffma2(acc2[qi], pack2(p4.y, p4.y), v1);
                ffma2(acc2[qi], pack2(p4.z, p4.z), v2);
                ffma2(acc2[qi], pack2(p4.w, p4.w), v3);
            }
        }
        __syncthreads();  // all warps done with K_s/V_s[buf] before it gets refilled
    }

    // ---- write split partials ----
    #pragma unroll
    for (int qi = 0; qi < QW; qi++) {
        const int qg = q0 + w * QW + qi;
        float2 a = unpack2(acc2[qi]);
        *(float2*)&g_pacc[split][qg][h][2 * lane] = a;
        if (lane == 0) {
            g_pm[split][qg][h] = m_run[qi];
            g_pl[split][qg][h] = l_run[qi];
        }
    }
}

// ---------------- split-K combine ----------------
__global__ void combine_kernel(float* __restrict__ Y) {
    const int i = blockIdx.x * blockDim.x + threadIdx.x;  // over S*H*D
    if (i >= S_ * H_ * D_) return;
    const int q = i / (H_ * D_);
    const int hd = i % (H_ * D_);
    const int h = hd / D_;
    const int d = hd % D_;
    float m = -1e30f;
    #pragma unroll
    for (int s = 0; s < NSPLIT; s++) m = fmaxf(m, g_pm[s][q][h]);
    float lsum = 0.0f, asum = 0.0f;
    #pragma unroll
    for (int s = 0; s < NSPLIT; s++) {
        const float wgt = __expf(g_pm[s][q][h] - m);
        lsum += g_pl[s][q][h] * wgt;
        asum += g_pacc[s][q][h][d] * wgt;
    }
    Y[i] = asum / lsum;   // y layout [q][h][d] == linear i
}

extern "C" void kernel_launch(void* const* d_in, const int* in_sizes, int n_in,
                              void* d_out, int out_size) {
    const float* mk = (const float*)d_in[0];
    const float* mv = (const float*)d_in[1];
    const float* ks = (const float*)d_in[2];
    const float* vs = (const float*)d_in[3];
    const float* qs = (const float*)d_in[4];
    const unsigned char* sos = (n_in > 5) ? (const unsigned char*)d_in[5] : nullptr;
    const int* wip = (n_in > 6) ? (const int*)d_in[6] : nullptr;

    float* out = (float*)d_out;
    float* y  = out + OFF_Y;
    float* ok = out + OFF_MK;
    float* ov = out + OFF_MV;

    // 1) clear-copy memory into output buffer (keep factor read on device)
    copy_clear_kernel<<<(M_ * HD_ / 4 + 255) / 256, 256>>>(
        (const float4*)mk, (const float4*)mv, (float4*)ok, (float4*)ov, sos);

    // 2) attention over [cleared memory | causal segment], split-K partials
    dim3 ag(S_ / BQ, H_, NSPLIT);
    attn_kernel<<<ag, NTHREADS>>>(ok, ov, ks, vs, qs);

    // 3) combine partials -> y
    combine_kernel<<<(S_ * H_ * D_ + 255) / 256, 256>>>(y);

    // 4) scatter segment KV into ring buffer (after attention consumed cleared mem)
    scatter_kernel<<<(S_ * HD_ / 4 + 255) / 256, 256>>>(
        (const float4*)ks, (const float4*)vs, (float4*)ok, (float4*)ov, wip);

    // 5) new write index
    if (out_size > OFF_WI)
        widx_kernel<<<1, 1>>>(out + OFF_WI, wip);
}

// round 8
// speedup vs baseline: 6.5645x; 6.5645x over previous
#include <cuda_runtime.h>
#include <cuda_bf16.h>
#include <cstdint>

// Problem constants (DenseKVMemory: B=1, M=32768, S=512, H=8, D=64)
#define M_   32768
#define S_   512
#define H_   8
#define D_   64
#define HD_  (H_ * D_)          // 512
#define CTX_ (M_ + S_)          // 33280

#define TN        32            // keys per tile
#define KST       68            // smem row stride (floats): K b-frag loads conflict-free
#define NW        4             // warps per block
#define BQ        64            // queries per block (16 per warp)
#define NTHREADS  128
#define NSPLIT    4
#define NTILES    (CTX_ / TN)            // 1040
#define TPS       (NTILES / NSPLIT)      // 260

// Output layout: y | new_mem_keys | new_mem_vals | new_write_index
#define OFF_Y   0
#define OFF_MK  (S_ * HD_)                 // 262144
#define OFF_MV  (OFF_MK + M_ * HD_)        // 17039360
#define OFF_WI  (OFF_MV + M_ * HD_)        // 33816576

// Split-K partial scratch (device globals: no allocation allowed)
__device__ float g_pacc[NSPLIT][S_][H_][D_];   // 4 MB
__device__ float g_pm[NSPLIT][S_][H_];
__device__ float g_pl[NSPLIT][S_][H_];

// ---------------- helpers ----------------
__device__ __forceinline__ uint32_t f2tf(float x) {
    uint32_t r;
    asm("cvt.rna.tf32.f32 %0, %1;" : "=r"(r) : "f"(x));
    return r;
}
__device__ __forceinline__ void mma8(float* d, const uint32_t* a, uint32_t b0, uint32_t b1) {
    asm volatile(
        "mma.sync.aligned.m16n8k8.row.col.f32.tf32.tf32.f32 "
        "{%0,%1,%2,%3}, {%4,%5,%6,%7}, {%8,%9}, {%0,%1,%2,%3};\n"
        : "+f"(d[0]), "+f"(d[1]), "+f"(d[2]), "+f"(d[3])
        : "r"(a[0]), "r"(a[1]), "r"(a[2]), "r"(a[3]), "r"(b0), "r"(b1));
}
__device__ __forceinline__ void cp_async16(void* sdst, const void* gsrc) {
    unsigned sa = (unsigned)__cvta_generic_to_shared(sdst);
    asm volatile("cp.async.cg.shared.global [%0], [%1], 16;" :: "r"(sa), "l"(gsrc));
}

// ---------------- clear-copy: new_mem = mem * keep ----------------
__global__ void copy_clear_kernel(const float4* __restrict__ mk,
                                  const float4* __restrict__ mv,
                                  float4* __restrict__ ok, float4* __restrict__ ov,
                                  const unsigned char* __restrict__ sos) {
    const int i = blockIdx.x * blockDim.x + threadIdx.x;
    const float keep = (sos != nullptr && sos[0]) ? 0.0f : 1.0f;
    if (i < (M_ * HD_) / 4) {
        float4 a = mk[i];
        a.x *= keep; a.y *= keep; a.z *= keep; a.w *= keep;
        ok[i] = a;
        float4 b = mv[i];
        b.x *= keep; b.y *= keep; b.z *= keep; b.w *= keep;
        ov[i] = b;
    }
}

// ---------------- scatter: contiguous slice write at clamped write_index ----------------
__global__ void scatter_kernel(const float4* __restrict__ k4, const float4* __restrict__ v4,
                               float4* __restrict__ ok, float4* __restrict__ ov,
                               const int* __restrict__ wip) {
    const int i = blockIdx.x * blockDim.x + threadIdx.x;
    if (i < (S_ * HD_) / 4) {
        int wi = wip ? *wip : 0;
        int wic = wi < 0 ? 0 : (wi > (M_ - S_) ? (M_ - S_) : wi);  // dynamic_update_slice clamp
        const int base = wic * (HD_ / 4);
        ok[base + i] = k4[i];
        ov[base + i] = v4[i];
    }
}

__global__ void widx_kernel(float* __restrict__ out_wi, const int* __restrict__ wip) {
    int wi = wip ? *wip : 0;
    out_wi[0] = (float)((wi + S_) % M_);
}

// ---------------- flash attention, tf32 tensor-core (split-K partials) ----------------
__global__ void __launch_bounds__(NTHREADS)
attn_kernel(const float* __restrict__ memK, const float* __restrict__ memV,
            const float* __restrict__ segK, const float* __restrict__ segV,
            const float* __restrict__ Qg) {
    __shared__ __align__(16) float K_s[2][TN][KST];
    __shared__ __align__(16) float V_s[2][TN][KST];
    __shared__ __align__(8)  float P_s[NW][16][TN + 4];   // tf32 bit patterns

    const int tid   = threadIdx.x;
    const int w     = tid >> 5;
    const int lane  = tid & 31;
    const int g     = lane >> 2;      // row group 0..7
    const int l4    = lane & 3;
    const int h     = blockIdx.y;
    const int q0    = blockIdx.x * BQ;
    const int split = blockIdx.z;
    const int t0    = split * TPS;

    const int qr0 = q0 + w * 16 + g;   // this thread's query rows
    const int qr1 = qr0 + 8;

    // ---- Q fragments in registers (pre-scaled, tf32-rounded) ----
    uint32_t qa[8][4];
    #pragma unroll
    for (int kc = 0; kc < 8; kc++) {
        const int d0 = kc * 8 + l4;
        qa[kc][0] = f2tf(Qg[(qr0 * H_ + h) * D_ + d0]     * 0.125f);
        qa[kc][1] = f2tf(Qg[(qr1 * H_ + h) * D_ + d0]     * 0.125f);
        qa[kc][2] = f2tf(Qg[(qr0 * H_ + h) * D_ + d0 + 4] * 0.125f);
        qa[kc][3] = f2tf(Qg[(qr1 * H_ + h) * D_ + d0 + 4] * 0.125f);
    }

    // ---- async tile loader ----
    const int lr  = tid >> 4;             // 0..7 base row
    const int lch = (tid & 15) * 4;       // 16B chunk within 64-float row
    auto issue_tile = [&](int t, int buf) {
        const int c0 = t * TN;
        const bool mem = (c0 < M_);
        const float* Ksrc = mem ? memK : segK;
        const float* Vsrc = mem ? memV : segV;
        const int row0 = mem ? c0 : (c0 - M_);
        #pragma unroll
        for (int rep = 0; rep < 4; rep++) {
            const int row = lr + rep * 8;
            const long goff = (long)(row0 + row) * HD_ + h * D_ + lch;
            cp_async16(&K_s[buf][row][lch], Ksrc + goff);
            cp_async16(&V_s[buf][row][lch], Vsrc + goff);
        }
    };

    float m0 = -1e30f, m1 = -1e30f, l0 = 0.0f, l1 = 0.0f;
    float o[8][4];
    #pragma unroll
    for (int jn = 0; jn < 8; jn++)
        #pragma unroll
        for (int e = 0; e < 4; e++) o[jn][e] = 0.0f;

    issue_tile(t0, 0);
    asm volatile("cp.async.commit_group;" ::: "memory");

    for (int tt = 0; tt < TPS; tt++) {
        const int t = t0 + tt;
        const int buf = tt & 1;
        if (tt + 1 < TPS) issue_tile(t + 1, buf ^ 1);
        asm volatile("cp.async.commit_group;" ::: "memory");
        asm volatile("cp.async.wait_group 1;" ::: "memory");
        __syncthreads();

        // ---- S = Q K^T : 16q x 32k per warp ----
        float s[4][4];
        #pragma unroll
        for (int jn = 0; jn < 4; jn++)
            #pragma unroll
            for (int e = 0; e < 4; e++) s[jn][e] = 0.0f;

        #pragma unroll
        for (int kc = 0; kc < 8; kc++) {
            #pragma unroll
            for (int jn = 0; jn < 4; jn++) {
                const uint32_t b0 = __float_as_uint(K_s[buf][jn * 8 + g][kc * 8 + l4]);
                const uint32_t b1 = __float_as_uint(K_s[buf][jn * 8 + g][kc * 8 + l4 + 4]);
                mma8(s[jn], qa[kc], b0, b1);
            }
        }

        // ---- causal mask (seg tiles only; tile type is uniform) ----
        const int kbase = t * TN;
        if (kbase >= M_) {
            #pragma unroll
            for (int jn = 0; jn < 4; jn++) {
                const int kg = kbase - M_ + jn * 8 + 2 * l4;
                if (kg     >= qr0) s[jn][0] = -1e30f;
                if (kg + 1 >= qr0) s[jn][1] = -1e30f;
                if (kg     >= qr1) s[jn][2] = -1e30f;
                if (kg + 1 >= qr1) s[jn][3] = -1e30f;
            }
        }

        // ---- online softmax ----
        float mx0 = s[0][0], mx1 = s[0][2];
        #pragma unroll
        for (int jn = 0; jn < 4; jn++) {
            mx0 = fmaxf(mx0, fmaxf(s[jn][0], s[jn][1]));
            mx1 = fmaxf(mx1, fmaxf(s[jn][2], s[jn][3]));
        }
        mx0 = fmaxf(mx0, __shfl_xor_sync(0xffffffffu, mx0, 1));
        mx0 = fmaxf(mx0, __shfl_xor_sync(0xffffffffu, mx0, 2));
        mx1 = fmaxf(mx1, __shfl_xor_sync(0xffffffffu, mx1, 1));
        mx1 = fmaxf(mx1, __shfl_xor_sync(0xffffffffu, mx1, 2));

        const float nm0 = fmaxf(m0, mx0);
        const float nm1 = fmaxf(m1, mx1);
        const float rs0 = __expf(m0 - nm0);
        const float rs1 = __expf(m1 - nm1);
        m0 = nm0; m1 = nm1;
        l0 *= rs0; l1 *= rs1;
        #pragma unroll
        for (int jn = 0; jn < 8; jn++) {
            o[jn][0] *= rs0; o[jn][1] *= rs0;
            o[jn][2] *= rs1; o[jn][3] *= rs1;
        }

        float sum0 = 0.0f, sum1 = 0.0f;
        #pragma unroll
        for (int jn = 0; jn < 4; jn++) {
            const float p00 = __expf(s[jn][0] - m0);
            const float p01 = __expf(s[jn][1] - m0);
            const float p10 = __expf(s[jn][2] - m1);
            const float p11 = __expf(s[jn][3] - m1);
            sum0 += p00 + p01;
            sum1 += p10 + p11;
            float2 t0v, t1v;
            t0v.x = __uint_as_float(f2tf(p00)); t0v.y = __uint_as_float(f2tf(p01));
            t1v.x = __uint_as_float(f2tf(p10)); t1v.y = __uint_as_float(f2tf(p11));
            *(float2*)&P_s[w][g][jn * 8 + 2 * l4]     = t0v;
            *(float2*)&P_s[w][g + 8][jn * 8 + 2 * l4] = t1v;
        }
        sum0 += __shfl_xor_sync(0xffffffffu, sum0, 1);
        sum0 += __shfl_xor_sync(0xffffffffu, sum0, 2);
        sum1 += __shfl_xor_sync(0xffffffffu, sum1, 1);
        sum1 += __shfl_xor_sync(0xffffffffu, sum1, 2);
        l0 += sum0; l1 += sum1;
        __syncwarp();

        // ---- O += P @ V : 16q x 64d per warp ----
        #pragma unroll
        for (int kc = 0; kc < 4; kc++) {
            uint32_t pa[4];
            pa[0] = *(const uint32_t*)&P_s[w][g][kc * 8 + l4];
            pa[1] = *(const uint32_t*)&P_s[w][g + 8][kc * 8 + l4];
            pa[2] = *(const uint32_t*)&P_s[w][g][kc * 8 + l4 + 4];
            pa[3] = *(const uint32_t*)&P_s[w][g + 8][kc * 8 + l4 + 4];
            #pragma unroll
            for (int jn = 0; jn < 8; jn++) {
                const uint32_t b0 = __float_as_uint(V_s[buf][kc * 8 + l4][jn * 8 + g]);
                const uint32_t b1 = __float_as_uint(V_s[buf][kc * 8 + l4 + 4][jn * 8 + g]);
                mma8(o[jn], pa, b0, b1);
            }
        }
        __syncthreads();   // all warps done with buf before it is refilled
    }

    // ---- write split partials ----
    #pragma unroll
    for (int jn = 0; jn < 8; jn++) {
        const int d = jn * 8 + 2 * l4;
        *(float2*)&g_pacc[split][qr0][h][d] = make_float2(o[jn][0], o[jn][1]);
        *(float2*)&g_pacc[split][qr1][h][d] = make_float2(o[jn][2], o[jn][3]);
    }
    if (l4 == 0) {
        g_pm[split][qr0][h] = m0; g_pl[split][qr0][h] = l0;
        g_pm[split][qr1][h] = m1; g_pl[split][qr1][h] = l1;
    }
}

// ---------------- split-K combine ----------------
__global__ void combine_kernel(float* __restrict__ Y) {
    const int i = blockIdx.x * blockDim.x + threadIdx.x;  // over S*H*D
    if (i >= S_ * H_ * D_) return;
    const int q = i / (H_ * D_);
    const int hd = i % (H_ * D_);
    const int h = hd / D_;
    const int d = hd % D_;
    float m = -1e30f;
    #pragma unroll
    for (int s = 0; s < NSPLIT; s++) m = fmaxf(m, g_pm[s][q][h]);
    float lsum = 0.0f, asum = 0.0f;
    #pragma unroll
    for (int s = 0; s < NSPLIT; s++) {
        const float wgt = __expf(g_pm[s][q][h] - m);
        lsum += g_pl[s][q][h] * wgt;
        asum += g_pacc[s][q][h][d] * wgt;
    }
    Y[i] = asum / lsum;   // y layout [q][h][d] == linear i
}

extern "C" void kernel_launch(void* const* d_in, const int* in_sizes, int n_in,
                              void* d_out, int out_size) {
    const float* mk = (const float*)d_in[0];
    const float* mv = (const float*)d_in[1];
    const float* ks = (const float*)d_in[2];
    const float* vs = (const float*)d_in[3];
    const float* qs = (const float*)d_in[4];
    const unsigned char* sos = (n_in > 5) ? (const unsigned char*)d_in[5] : nullptr;
    const int* wip = (n_in > 6) ? (const int*)d_in[6] : nullptr;

    float* out = (float*)d_out;
    float* y  = out + OFF_Y;
    float* ok = out + OFF_MK;
    float* ov = out + OFF_MV;

    // 1) clear-copy memory into output buffer (keep factor read on device)
    copy_clear_kernel<<<(M_ * HD_ / 4 + 255) / 256, 256>>>(
        (const float4*)mk, (const float4*)mv, (float4*)ok, (float4*)ov, sos);

    // 2) attention over [cleared memory | causal segment], split-K partials
    dim3 ag(S_ / BQ, H_, NSPLIT);
    attn_kernel<<<ag, NTHREADS>>>(ok, ov, ks, vs, qs);

    // 3) combine partials -> y
    combine_kernel<<<(S_ * H_ * D_ + 255) / 256, 256>>>(y);

    // 4) scatter segment KV into ring buffer (after attention consumed cleared mem)
    scatter_kernel<<<(S_ * HD_ / 4 + 255) / 256, 256>>>(
        (const float4*)ks, (const float4*)vs, (float4*)ok, (float4*)ov, wip);

    // 5) new write index
    if (out_size > OFF_WI)
        widx_kernel<<<1, 1>>>(out + OFF_WI, wip);
}

// round 9
// speedup vs baseline: 9.3464x; 1.4238x over previous
#include <cuda_runtime.h>
#include <cuda_bf16.h>
#include <cstdint>

// Problem constants (DenseKVMemory: B=1, M=32768, S=512, H=8, D=64)
#define M_   32768
#define S_   512
#define H_   8
#define D_   64
#define HD_  (H_ * D_)          // 512
#define CTX_ (M_ + S_)          // 33280

#define TN        32            // keys per tile
#define KSTK      68            // K smem row stride (68 % 32 == 4 -> QK b-frag conflict-free)
#define KSTV      72            // V smem row stride (72 % 32 == 8 -> PV b-frag conflict-free)
#define PST       36            // P^T smem stride   (36 % 16 == 4 -> P st/ld conflict-free)
#define NW        4             // warps per block
#define BQ        128           // queries per block (32 per warp)
#define NTHREADS  128
#define NSPLIT    8
#define NTILES    (CTX_ / TN)            // 1040
#define TPS       (NTILES / NSPLIT)      // 130

// dynamic smem layout (floats)
#define K_OFF 0
#define V_OFF (2 * TN * KSTK)                  // 4352
#define P_OFF (V_OFF + 2 * TN * KSTV)          // 8960
#define SMEM_FLOATS (P_OFF + NW * TN * PST)    // 13568
#define SMEM_BYTES  (SMEM_FLOATS * 4)          // 54272

#define KIDX(b,r,c) (K_OFF + (b) * (TN * KSTK) + (r) * KSTK + (c))
#define VIDX(b,r,c) (V_OFF + (b) * (TN * KSTV) + (r) * KSTV + (c))
#define PIDX(w,k,q) (P_OFF + (w) * (TN * PST) + (k) * PST + (q))

// Output layout: y | new_mem_keys | new_mem_vals | new_write_index
#define OFF_Y   0
#define OFF_MK  (S_ * HD_)                 // 262144
#define OFF_MV  (OFF_MK + M_ * HD_)        // 17039360
#define OFF_WI  (OFF_MV + M_ * HD_)        // 33816576

// Split-K partial scratch (device globals: no allocation allowed)
__device__ float g_pacc[NSPLIT][S_][H_][D_];   // 8 MB
__device__ float g_pm[NSPLIT][S_][H_];
__device__ float g_pl[NSPLIT][S_][H_];

// ---------------- helpers ----------------
__device__ __forceinline__ uint32_t f2tf(float x) {
    uint32_t r;
    asm("cvt.rna.tf32.f32 %0, %1;" : "=r"(r) : "f"(x));
    return r;
}
__device__ __forceinline__ void mma8(float* d, const uint32_t* a, uint32_t b0, uint32_t b1) {
    asm volatile(
        "mma.sync.aligned.m16n8k8.row.col.f32.tf32.tf32.f32 "
        "{%0,%1,%2,%3}, {%4,%5,%6,%7}, {%8,%9}, {%0,%1,%2,%3};\n"
        : "+f"(d[0]), "+f"(d[1]), "+f"(d[2]), "+f"(d[3])
        : "r"(a[0]), "r"(a[1]), "r"(a[2]), "r"(a[3]), "r"(b0), "r"(b1));
}
__device__ __forceinline__ void cp_async16(void* sdst, const void* gsrc) {
    unsigned sa = (unsigned)__cvta_generic_to_shared(sdst);
    asm volatile("cp.async.cg.shared.global [%0], [%1], 16;" :: "r"(sa), "l"(gsrc));
}

// ---------------- clear-copy: new_mem = mem * keep ----------------
__global__ void copy_clear_kernel(const float4* __restrict__ mk,
                                  const float4* __restrict__ mv,
                                  float4* __restrict__ ok, float4* __restrict__ ov,
                                  const unsigned char* __restrict__ sos) {
    const int i = blockIdx.x * blockDim.x + threadIdx.x;
    const float keep = (sos != nullptr && sos[0]) ? 0.0f : 1.0f;
    if (i < (M_ * HD_) / 4) {
        float4 a = mk[i];
        a.x *= keep; a.y *= keep; a.z *= keep; a.w *= keep;
        ok[i] = a;
        float4 b = mv[i];
        b.x *= keep; b.y *= keep; b.z *= keep; b.w *= keep;
        ov[i] = b;
    }
}

// ---------------- scatter: contiguous slice write at clamped write_index ----------------
__global__ void scatter_kernel(const float4* __restrict__ k4, const float4* __restrict__ v4,
                               float4* __restrict__ ok, float4* __restrict__ ov,
                               const int* __restrict__ wip) {
    const int i = blockIdx.x * blockDim.x + threadIdx.x;
    if (i < (S_ * HD_) / 4) {
        int wi = wip ? *wip : 0;
        int wic = wi < 0 ? 0 : (wi > (M_ - S_) ? (M_ - S_) : wi);  // dynamic_update_slice clamp
        const int base = wic * (HD_ / 4);
        ok[base + i] = k4[i];
        ov[base + i] = v4[i];
    }
}

__global__ void widx_kernel(float* __restrict__ out_wi, const int* __restrict__ wip) {
    int wi = wip ? *wip : 0;
    out_wi[0] = (float)((wi + S_) % M_);
}

// ---------------- flash attention, tf32 tensor-core, 32q/warp (split-K partials) ----------------
__global__ void __launch_bounds__(NTHREADS)
attn_kernel(const float* __restrict__ memK, const float* __restrict__ memV,
            const float* __restrict__ segK, const float* __restrict__ segV,
            const float* __restrict__ Qg) {
    extern __shared__ __align__(16) float sm[];

    const int tid   = threadIdx.x;
    const int w     = tid >> 5;
    const int lane  = tid & 31;
    const int g     = lane >> 2;      // row group 0..7
    const int l4    = lane & 3;
    const int h     = blockIdx.y;
    const int q0    = blockIdx.x * BQ;
    const int split = blockIdx.z;
    const int t0    = split * TPS;

    const int qbase = q0 + w * 32;    // warp owns 32 consecutive queries

    // ---- Q fragments in registers (pre-scaled, tf32-rounded): 2 m16 halves ----
    uint32_t qa[8][8];
    #pragma unroll
    for (int kc = 0; kc < 8; kc++) {
        #pragma unroll
        for (int hh = 0; hh < 2; hh++) {
            const int qr0 = qbase + hh * 16 + g;
            const int qr1 = qr0 + 8;
            const int d0 = kc * 8 + l4;
            qa[kc][hh * 4 + 0] = f2tf(Qg[(qr0 * H_ + h) * D_ + d0]     * 0.125f);
            qa[kc][hh * 4 + 1] = f2tf(Qg[(qr1 * H_ + h) * D_ + d0]     * 0.125f);
            qa[kc][hh * 4 + 2] = f2tf(Qg[(qr0 * H_ + h) * D_ + d0 + 4] * 0.125f);
            qa[kc][hh * 4 + 3] = f2tf(Qg[(qr1 * H_ + h) * D_ + d0 + 4] * 0.125f);
        }
    }

    // ---- async tile loader ----
    const int lr  = tid >> 4;             // 0..7 base row
    const int lch = (tid & 15) * 4;       // 16B chunk within 64-float row
    auto issue_tile = [&](int t, int buf) {
        const int c0 = t * TN;
        const bool mem = (c0 < M_);
        const float* Ksrc = mem ? memK : segK;
        const float* Vsrc = mem ? memV : segV;
        const int row0 = mem ? c0 : (c0 - M_);
        #pragma unroll
        for (int rep = 0; rep < 4; rep++) {
            const int row = lr + rep * 8;
            const long goff = (long)(row0 + row) * HD_ + h * D_ + lch;
            cp_async16(&sm[KIDX(buf, row, lch)], Ksrc + goff);
            cp_async16(&sm[VIDX(buf, row, lch)], Vsrc + goff);
        }
    };

    float m[2][2], l[2][2];
    float o[2][8][4];
    #pragma unroll
    for (int hh = 0; hh < 2; hh++) {
        m[hh][0] = -1e30f; m[hh][1] = -1e30f;
        l[hh][0] = 0.0f;   l[hh][1] = 0.0f;
        #pragma unroll
        for (int jn = 0; jn < 8; jn++)
            #pragma unroll
            for (int e = 0; e < 4; e++) o[hh][jn][e] = 0.0f;
    }

    issue_tile(t0, 0);
    asm volatile("cp.async.commit_group;" ::: "memory");

    for (int tt = 0; tt < TPS; tt++) {
        const int t = t0 + tt;
        const int buf = tt & 1;
        if (tt + 1 < TPS) issue_tile(t + 1, buf ^ 1);
        asm volatile("cp.async.commit_group;" ::: "memory");
        asm volatile("cp.async.wait_group 1;" ::: "memory");
        __syncthreads();

        // ---- S = Q K^T : 32q x 32k per warp (K b-frags shared by both halves) ----
        float s[2][4][4];
        #pragma unroll
        for (int hh = 0; hh < 2; hh++)
            #pragma unroll
            for (int jn = 0; jn < 4; jn++)
                #pragma unroll
                for (int e = 0; e < 4; e++) s[hh][jn][e] = 0.0f;

        #pragma unroll
        for (int kc = 0; kc < 8; kc++) {
            #pragma unroll
            for (int jn = 0; jn < 4; jn++) {
                const uint32_t b0 = __float_as_uint(sm[KIDX(buf, jn * 8 + g, kc * 8 + l4)]);
                const uint32_t b1 = __float_as_uint(sm[KIDX(buf, jn * 8 + g, kc * 8 + l4 + 4)]);
                mma8(s[0][jn], &qa[kc][0], b0, b1);
                mma8(s[1][jn], &qa[kc][4], b0, b1);
            }
        }

        // ---- causal mask (seg tiles only; tile type is uniform) ----
        const int kbase = t * TN;
        if (kbase >= M_) {
            #pragma unroll
            for (int hh = 0; hh < 2; hh++) {
                const int qr0 = qbase + hh * 16 + g;
                const int qr1 = qr0 + 8;
                #pragma unroll
                for (int jn = 0; jn < 4; jn++) {
                    const int kg = kbase - M_ + jn * 8 + 2 * l4;
                    if (kg     >= qr0) s[hh][jn][0] = -1e30f;
                    if (kg + 1 >= qr0) s[hh][jn][1] = -1e30f;
                    if (kg     >= qr1) s[hh][jn][2] = -1e30f;
                    if (kg + 1 >= qr1) s[hh][jn][3] = -1e30f;
                }
            }
        }

        // ---- online softmax (per half) ----
        #pragma unroll
        for (int hh = 0; hh < 2; hh++) {
            float mx0 = s[hh][0][0], mx1 = s[hh][0][2];
            #pragma unroll
            for (int jn = 0; jn < 4; jn++) {
                mx0 = fmaxf(mx0, fmaxf(s[hh][jn][0], s[hh][jn][1]));
                mx1 = fmaxf(mx1, fmaxf(s[hh][jn][2], s[hh][jn][3]));
            }
            mx0 = fmaxf(mx0, __shfl_xor_sync(0xffffffffu, mx0, 1));
            mx0 = fmaxf(mx0, __shfl_xor_sync(0xffffffffu, mx0, 2));
            mx1 = fmaxf(mx1, __shfl_xor_sync(0xffffffffu, mx1, 1));
            mx1 = fmaxf(mx1, __shfl_xor_sync(0xffffffffu, mx1, 2));

            const float nm0 = fmaxf(m[hh][0], mx0);
            const float nm1 = fmaxf(m[hh][1], mx1);
            const bool need = (nm0 > m[hh][0]) || (nm1 > m[hh][1]);
            if (__any_sync(0xffffffffu, need)) {
                const float rs0 = __expf(m[hh][0] - nm0);
                const float rs1 = __expf(m[hh][1] - nm1);
                m[hh][0] = nm0; m[hh][1] = nm1;
                l[hh][0] *= rs0; l[hh][1] *= rs1;
                #pragma unroll
                for (int jn = 0; jn < 8; jn++) {
                    o[hh][jn][0] *= rs0; o[hh][jn][1] *= rs0;
                    o[hh][jn][2] *= rs1; o[hh][jn][3] *= rs1;
                }
            }

            float sum0 = 0.0f, sum1 = 0.0f;
            #pragma unroll
            for (int jn = 0; jn < 4; jn++) {
                const float p00 = __expf(s[hh][jn][0] - m[hh][0]);
                const float p01 = __expf(s[hh][jn][1] - m[hh][0]);
                const float p10 = __expf(s[hh][jn][2] - m[hh][1]);
                const float p11 = __expf(s[hh][jn][3] - m[hh][1]);
                sum0 += p00 + p01;
                sum1 += p10 + p11;
                // P stored transposed [k][q] as tf32 bit patterns (conflict-free)
                const int kr = jn * 8 + 2 * l4;
                sm[PIDX(w, kr,     hh * 16 + g)]     = __uint_as_float(f2tf(p00));
                sm[PIDX(w, kr + 1, hh * 16 + g)]     = __uint_as_float(f2tf(p01));
                sm[PIDX(w, kr,     hh * 16 + 8 + g)] = __uint_as_float(f2tf(p10));
                sm[PIDX(w, kr + 1, hh * 16 + 8 + g)] = __uint_as_float(f2tf(p11));
            }
            sum0 += __shfl_xor_sync(0xffffffffu, sum0, 1);
            sum0 += __shfl_xor_sync(0xffffffffu, sum0, 2);
            sum1 += __shfl_xor_sync(0xffffffffu, sum1, 1);
            sum1 += __shfl_xor_sync(0xffffffffu, sum1, 2);
            l[hh][0] += sum0; l[hh][1] += sum1;
        }
        __syncwarp();

        // ---- O += P @ V : 32q x 64d per warp (V b-frags shared by both halves) ----
        #pragma unroll
        for (int kc = 0; kc < 4; kc++) {
            uint32_t pa0[4], pa1[4];
            pa0[0] = __float_as_uint(sm[PIDX(w, kc * 8 + l4,     g)]);
            pa0[1] = __float_as_uint(sm[PIDX(w, kc * 8 + l4,     8 + g)]);
            pa0[2] = __float_as_uint(sm[PIDX(w, kc * 8 + l4 + 4, g)]);
            pa0[3] = __float_as_uint(sm[PIDX(w, kc * 8 + l4 + 4, 8 + g)]);
            pa1[0] = __float_as_uint(sm[PIDX(w, kc * 8 + l4,     16 + g)]);
            pa1[1] = __float_as_uint(sm[PIDX(w, kc * 8 + l4,     24 + g)]);
            pa1[2] = __float_as_uint(sm[PIDX(w, kc * 8 + l4 + 4, 16 + g)]);
            pa1[3] = __float_as_uint(sm[PIDX(w, kc * 8 + l4 + 4, 24 + g)]);
            #pragma unroll
            for (int jn = 0; jn < 8; jn++) {
                const uint32_t b0 = __float_as_uint(sm[VIDX(buf, kc * 8 + l4,     jn * 8 + g)]);
                const uint32_t b1 = __float_as_uint(sm[VIDX(buf, kc * 8 + l4 + 4, jn * 8 + g)]);
                mma8(o[0][jn], pa0, b0, b1);
                mma8(o[1][jn], pa1, b0, b1);
            }
        }
        __syncthreads();   // all warps done with buf before it is refilled
    }

    // ---- write split partials ----
    #pragma unroll
    for (int hh = 0; hh < 2; hh++) {
        const int qr0 = qbase + hh * 16 + g;
        const int qr1 = qr0 + 8;
        #pragma unroll
        for (int jn = 0; jn < 8; jn++) {
            const int d = jn * 8 + 2 * l4;
            *(float2*)&g_pacc[split][qr0][h][d] = make_float2(o[hh][jn][0], o[hh][jn][1]);
            *(float2*)&g_pacc[split][qr1][h][d] = make_float2(o[hh][jn][2], o[hh][jn][3]);
        }
        if (l4 == 0) {
            g_pm[split][qr0][h] = m[hh][0]; g_pl[split][qr0][h] = l[hh][0];
            g_pm[split][qr1][h] = m[hh][1]; g_pl[split][qr1][h] = l[hh][1];
        }
    }
}

// ---------------- split-K combine ----------------
__global__ void combine_kernel(float* __restrict__ Y) {
    const int i = blockIdx.x * blockDim.x + threadIdx.x;  // over S*H*D
    if (i >= S_ * H_ * D_) return;
    const int q = i / (H_ * D_);
    const int hd = i % (H_ * D_);
    const int h = hd / D_;
    const int d = hd % D_;
    float m = -1e30f;
    #pragma unroll
    for (int s = 0; s < NSPLIT; s++) m = fmaxf(m, g_pm[s][q][h]);
    float lsum = 0.0f, asum = 0.0f;
    #pragma unroll
    for (int s = 0; s < NSPLIT; s++) {
        const float wgt = __expf(g_pm[s][q][h] - m);
        lsum += g_pl[s][q][h] * wgt;
        asum += g_pacc[s][q][h][d] * wgt;
    }
    Y[i] = asum / lsum;   // y layout [q][h][d] == linear i
}

extern "C" void kernel_launch(void* const* d_in, const int* in_sizes, int n_in,
                              void* d_out, int out_size) {
    const float* mk = (const float*)d_in[0];
    const float* mv = (const float*)d_in[1];
    const float* ks = (const float*)d_in[2];
    const float* vs = (const float*)d_in[3];
    const float* qs = (const float*)d_in[4];
    const unsigned char* sos = (n_in > 5) ? (const unsigned char*)d_in[5] : nullptr;
    const int* wip = (n_in > 6) ? (const int*)d_in[6] : nullptr;

    float* out = (float*)d_out;
    float* y  = out + OFF_Y;
    float* ok = out + OFF_MK;
    float* ov = out + OFF_MV;

    // opt-in to >48KB dynamic smem (idempotent; host-side attribute, not a stream op)
    cudaFuncSetAttribute(attn_kernel, cudaFuncAttributeMaxDynamicSharedMemorySize, SMEM_BYTES);

    // 1) clear-copy memory into output buffer (keep factor read on device)
    copy_clear_kernel<<<(M_ * HD_ / 4 + 255) / 256, 256>>>(
        (const float4*)mk, (const float4*)mv, (float4*)ok, (float4*)ov, sos);

    // 2) attention over [cleared memory | causal segment], split-K partials
    dim3 ag(S_ / BQ, H_, NSPLIT);
    attn_kernel<<<ag, NTHREADS, SMEM_BYTES>>>(ok, ov, ks, vs, qs);

    // 3) combine partials -> y
    combine_kernel<<<(S_ * H_ * D_ + 255) / 256, 256>>>(y);

    // 4) scatter segment KV into ring buffer (after attention consumed cleared mem)
    scatter_kernel<<<(S_ * HD_ / 4 + 255) / 256, 256>>>(
        (const float4*)ks, (const float4*)vs, (float4*)ok, (float4*)ov, wip);

    // 5) new write index
    if (out_size > OFF_WI)
        widx_kernel<<<1, 1>>>(out + OFF_WI, wip);
}